// round 9
// baseline (speedup 1.0000x reference)
#include <cuda_runtime.h>

#define FULL 0xffffffffu

#define MAX_B 8192
__device__ float g_x[MAX_B * 17 * 64];     // aggregated activations per (elem,row)
__device__ float g_attn[MAX_B * 16];       // hop-0 attention (reused in iter-1)

__device__ __forceinline__ float sigmoidf_(float y) {
    return __fdividef(1.f, 1.f + __expf(-y));
}

// ---------------- Kernel A: gather + attention + aggregation ----------------
// One CTA per 4 elements, 256 threads, ~48 regs -> 5-6 CTAs/SM (40+ warps).
// Phase C identical to R8 (4 interleaved chains, 68 LDG.128 in flight/warp),
// but x rows go straight to global scratch.
__global__ void __launch_bounds__(256, 6) kgcn_gather_kernel(
    const int* __restrict__ U, const int* __restrict__ V,
    const int* __restrict__ adj_ent, const int* __restrict__ adj_rel,
    const float* __restrict__ usr_emb, const float* __restrict__ rel_emb,
    const float* __restrict__ ent_emb, int NR)
{
    __shared__ float user_sh[4][64];
    __shared__ float urel_sh[4][32];
    __shared__ int   nbr_sh[4][272];   // [0..255] hop2 ents, [256..271] hop1 ents
    __shared__ int   rel_sh[4][272];

    const int tid  = threadIdx.x;
    const int col  = tid & 63;
    const int lane = tid & 31;
    const int w    = tid >> 5;

    const int b0 = 4 * blockIdx.x;
    int uu[4], vv[4];
    #pragma unroll
    for (int e = 0; e < 4; e++) { uu[e] = U[b0 + e]; vv[e] = V[b0 + e]; }

    // Phase A: stage users + hop-1 adjacency
    user_sh[tid >> 6][col] = usr_emb[uu[tid >> 6] * 64 + col];
    if (tid < 64) {
        int e = tid >> 4, j = tid & 15;
        nbr_sh[e][256 + j] = adj_ent[vv[e] * 16 + j];
        rel_sh[e][256 + j] = adj_rel[vv[e] * 16 + j];
    }
    __syncthreads();

    // Phase B: hop-2 adjacency + urel tables
    {
        int j = tid & 15, pr = tid >> 4;
        #pragma unroll
        for (int e = 0; e < 4; e++) {
            int p = nbr_sh[e][256 + pr];
            nbr_sh[e][tid] = adj_ent[p * 16 + j];
            rel_sh[e][tid] = adj_rel[p * 16 + j];
        }
    }
    {
        int r = tid >> 3;
        int c = (tid & 7) * 8;
        float pa[4] = {0.f, 0.f, 0.f, 0.f};
        if (r < NR) {
            const float4* rp = (const float4*)(rel_emb + r * 64 + c);
            float4 aa = rp[0], bb = rp[1];
            #pragma unroll
            for (int e = 0; e < 4; e++)
                pa[e] = aa.x * user_sh[e][c+0] + aa.y * user_sh[e][c+1]
                      + aa.z * user_sh[e][c+2] + aa.w * user_sh[e][c+3]
                      + bb.x * user_sh[e][c+4] + bb.y * user_sh[e][c+5]
                      + bb.z * user_sh[e][c+6] + bb.w * user_sh[e][c+7];
        }
        #pragma unroll
        for (int o = 4; o > 0; o >>= 1) {
            #pragma unroll
            for (int e = 0; e < 4; e++)
                pa[e] += __shfl_down_sync(FULL, pa[e], o);
        }
        if ((tid & 7) == 0 && r < NR) {
            #pragma unroll
            for (int e = 0; e < 4; e++) urel_sh[e][r] = pa[e];
        }
    }
    __syncthreads();

    // Phase C: fused softmax + float4 aggregation, 4 elems interleaved
    {
        const int hlf16 = lane & 16;
        const int k15   = lane & 15;
        const int myrow = 2 * w + (lane >> 4);
        const float4* entf4 = (const float4*)ent_emb;

        float sc[4], mx[4], ev[4], sm[4], pp[4];
        #pragma unroll
        for (int e = 0; e < 4; e++)
            sc[e] = urel_sh[e][rel_sh[e][(myrow << 4) + k15]];
        #pragma unroll
        for (int e = 0; e < 4; e++) mx[e] = sc[e];
        #pragma unroll
        for (int o = 8; o > 0; o >>= 1) {
            #pragma unroll
            for (int e = 0; e < 4; e++)
                mx[e] = fmaxf(mx[e], __shfl_xor_sync(FULL, mx[e], o));
        }
        #pragma unroll
        for (int e = 0; e < 4; e++) { ev[e] = __expf(sc[e] - mx[e]); sm[e] = ev[e]; }
        #pragma unroll
        for (int o = 8; o > 0; o >>= 1) {
            #pragma unroll
            for (int e = 0; e < 4; e++)
                sm[e] += __shfl_xor_sync(FULL, sm[e], o);
        }
        #pragma unroll
        for (int e = 0; e < 4; e++) pp[e] = __fdividef(ev[e], sm[e]);

        const int* nb[4];
        #pragma unroll
        for (int e = 0; e < 4; e++) nb[e] = &nbr_sh[e][myrow << 4];
        float4 acc[4];
        #pragma unroll
        for (int e = 0; e < 4; e++) acc[e] = make_float4(0.f, 0.f, 0.f, 0.f);
        #pragma unroll
        for (int k = 0; k < 16; k++) {
            #pragma unroll
            for (int e = 0; e < 4; e++) {
                float pk = __shfl_sync(FULL, pp[e], hlf16 + k);
                float4 t = entf4[(nb[e][k] << 4) + k15];
                acc[e].x = fmaf(pk, t.x, acc[e].x);
                acc[e].y = fmaf(pk, t.y, acc[e].y);
                acc[e].z = fmaf(pk, t.z, acc[e].z);
                acc[e].w = fmaf(pk, t.w, acc[e].w);
            }
        }
        #pragma unroll
        for (int e = 0; e < 4; e++) {
            float4 sv = entf4[(nbr_sh[e][256 + myrow] << 4) + k15];
            ((float4*)&g_x[(b0 + e) * 1088 + (myrow << 6)])[k15] = make_float4(
                sv.x + acc[e].x, sv.y + acc[e].y, sv.z + acc[e].z, sv.w + acc[e].w);
        }

        // hop-0 rows: warp e handles element e
        if (w < 4) {
            const int e = w;
            float s2 = urel_sh[e][rel_sh[e][256 + k15]];
            float mx2 = s2;
            mx2 = fmaxf(mx2, __shfl_xor_sync(FULL, mx2, 8));
            mx2 = fmaxf(mx2, __shfl_xor_sync(FULL, mx2, 4));
            mx2 = fmaxf(mx2, __shfl_xor_sync(FULL, mx2, 2));
            mx2 = fmaxf(mx2, __shfl_xor_sync(FULL, mx2, 1));
            float ev2 = __expf(s2 - mx2);
            float sm2 = ev2;
            sm2 += __shfl_xor_sync(FULL, sm2, 8);
            sm2 += __shfl_xor_sync(FULL, sm2, 4);
            sm2 += __shfl_xor_sync(FULL, sm2, 2);
            sm2 += __shfl_xor_sync(FULL, sm2, 1);
            float p2 = __fdividef(ev2, sm2);
            if (lane < 16) g_attn[(b0 + e) * 16 + lane] = p2;

            float4 acc2 = make_float4(0.f, 0.f, 0.f, 0.f);
            #pragma unroll
            for (int k = 0; k < 16; k++) {
                float pk = __shfl_sync(FULL, p2, hlf16 + k);
                float4 t = entf4[(nbr_sh[e][256 + k] << 4) + k15];
                acc2.x = fmaf(pk, t.x, acc2.x);
                acc2.y = fmaf(pk, t.y, acc2.y);
                acc2.z = fmaf(pk, t.z, acc2.z);
                acc2.w = fmaf(pk, t.w, acc2.w);
            }
            float4 sv2 = entf4[(vv[e] << 4) + k15];
            if (lane < 16)
                ((float4*)&g_x[(b0 + e) * 1088 + (16 << 6)])[k15] = make_float4(
                    sv2.x + acc2.x, sv2.y + acc2.y, sv2.z + acc2.z, sv2.w + acc2.w);
        }
    }
}

// ---------------- Kernel B: matvecs + iter-1 + final score ----------------
// One CTA per 4 elements, 256 threads. W half-column in 32 regs; matvec and
// Phase D warp-autonomous as in R8 (dot = 32 FMA + shfl_xor(16)).
__global__ void __launch_bounds__(256, 3) kgcn_matvec_kernel(
    const int* __restrict__ U,
    const float* __restrict__ usr_emb,
    const float* __restrict__ Wg, const float* __restrict__ bg,
    float* __restrict__ out)
{
    __shared__ float user_sh[4][64];
    __shared__ float attn16_sh[4][16];
    __shared__ __align__(16) float x_sh[4][17][64];
    __shared__ __align__(16) float h_sh[4][17][64];
    __shared__ __align__(16) float x2_sh[4][64];
    __shared__ float red2_sh[4][4];

    const int tid   = threadIdx.x;
    const int col   = tid & 63;
    const int lane  = tid & 31;
    const int w     = tid >> 5;
    const int chunk = w & 3;
    const int par   = w >> 2;
    const int halfL = lane >> 4;
    const int k15w  = lane & 15;
    const int mycol = chunk * 16 + k15w;

    const int b0 = 4 * blockIdx.x;

    // Stage: user rows, attn, x from scratch; W half-column -> regs
    user_sh[tid >> 6][col] = usr_emb[U[b0 + (tid >> 6)] * 64 + col];
    if (tid >= 64 && tid < 128) {
        int j = tid - 64;
        attn16_sh[j >> 4][j & 15] = g_attn[b0 * 16 + j];
    }
    {
        const float4* gx4 = (const float4*)&g_x[b0 * 1088];
        float4* x4 = (float4*)x_sh;
        #pragma unroll
        for (int i = 0; i < 5; i++) {
            int idx = tid + 256 * i;
            if (idx < 1088) x4[idx] = gx4[idx];
        }
    }
    float Wreg[32];
    #pragma unroll
    for (int dd = 0; dd < 32; dd++)
        Wreg[dd] = Wg[(halfL * 32 + dd) * 64 + mycol];
    const float bmy = bg[mycol];
    __syncthreads();

    // Matvec: warp-autonomous, zero interior barriers
    {
        for (int rr = par; rr <= 16; rr += 2) {
            float y0 = 0.f, y1 = 0.f, y2 = 0.f, y3 = 0.f;
            #pragma unroll
            for (int q = 0; q < 8; q++) {
                float wa = Wreg[4*q+0], wb = Wreg[4*q+1];
                float wc = Wreg[4*q+2], wd = Wreg[4*q+3];
                float4 v0 = *(const float4*)&x_sh[0][rr][halfL * 32 + 4*q];
                float4 v1 = *(const float4*)&x_sh[1][rr][halfL * 32 + 4*q];
                float4 v2 = *(const float4*)&x_sh[2][rr][halfL * 32 + 4*q];
                float4 v3 = *(const float4*)&x_sh[3][rr][halfL * 32 + 4*q];
                y0 = fmaf(v0.x, wa, y0); y0 = fmaf(v0.y, wb, y0);
                y0 = fmaf(v0.z, wc, y0); y0 = fmaf(v0.w, wd, y0);
                y1 = fmaf(v1.x, wa, y1); y1 = fmaf(v1.y, wb, y1);
                y1 = fmaf(v1.z, wc, y1); y1 = fmaf(v1.w, wd, y1);
                y2 = fmaf(v2.x, wa, y2); y2 = fmaf(v2.y, wb, y2);
                y2 = fmaf(v2.z, wc, y2); y2 = fmaf(v2.w, wd, y2);
                y3 = fmaf(v3.x, wa, y3); y3 = fmaf(v3.y, wb, y3);
                y3 = fmaf(v3.z, wc, y3); y3 = fmaf(v3.w, wd, y3);
            }
            float t0 = y0 + __shfl_xor_sync(FULL, y0, 16);
            float t1 = y1 + __shfl_xor_sync(FULL, y1, 16);
            float t2 = y2 + __shfl_xor_sync(FULL, y2, 16);
            float t3 = y3 + __shfl_xor_sync(FULL, y3, 16);
            if (halfL == 0) {
                h_sh[0][rr][mycol] = sigmoidf_(t0 + bmy);
                h_sh[1][rr][mycol] = sigmoidf_(t1 + bmy);
                h_sh[2][rr][mycol] = sigmoidf_(t2 + bmy);
                h_sh[3][rr][mycol] = sigmoidf_(t3 + bmy);
            }
        }
    }
    __syncthreads();

    // Iter-1 aggregation (thread per (e,col))
    {
        const int e = tid >> 6;
        float a0 = 0.f, a1 = 0.f, a2 = 0.f, a3 = 0.f;
        #pragma unroll
        for (int k = 0; k < 16; k += 4) {
            a0 = fmaf(attn16_sh[e][k + 0], h_sh[e][k + 0][col], a0);
            a1 = fmaf(attn16_sh[e][k + 1], h_sh[e][k + 1][col], a1);
            a2 = fmaf(attn16_sh[e][k + 2], h_sh[e][k + 2][col], a2);
            a3 = fmaf(attn16_sh[e][k + 3], h_sh[e][k + 3][col], a3);
        }
        x2_sh[e][col] = h_sh[e][16][col] + ((a0 + a1) + (a2 + a3));
    }
    __syncthreads();

    // Final matvec + tanh + dot(user) — warp-autonomous
    {
        for (int e = par; e < 4; e += 2) {
            float ya = 0.f, yb = 0.f;
            #pragma unroll
            for (int q = 0; q < 8; q += 2) {
                float4 v0 = *(const float4*)&x2_sh[e][halfL * 32 + 4*q];
                float4 v1 = *(const float4*)&x2_sh[e][halfL * 32 + 4*q + 4];
                ya = fmaf(v0.x, Wreg[4*q+0], ya); ya = fmaf(v0.y, Wreg[4*q+1], ya);
                ya = fmaf(v0.z, Wreg[4*q+2], ya); ya = fmaf(v0.w, Wreg[4*q+3], ya);
                yb = fmaf(v1.x, Wreg[4*q+4], yb); yb = fmaf(v1.y, Wreg[4*q+5], yb);
                yb = fmaf(v1.z, Wreg[4*q+6], yb); yb = fmaf(v1.w, Wreg[4*q+7], yb);
            }
            float y = ya + yb;
            float tot = y + __shfl_xor_sync(FULL, y, 16);
            float item = tanhf(tot + bmy);
            float t = user_sh[e][mycol] * item;   // lanes L, L+16 duplicate
            t += __shfl_xor_sync(FULL, t, 8);
            t += __shfl_xor_sync(FULL, t, 4);
            t += __shfl_xor_sync(FULL, t, 2);
            t += __shfl_xor_sync(FULL, t, 1);
            if (lane == 0) red2_sh[e][chunk] = t;
        }
    }
    __syncthreads();
    if (tid < 4)
        out[b0 + tid] = sigmoidf_((red2_sh[tid][0] + red2_sh[tid][1]) +
                                  (red2_sh[tid][2] + red2_sh[tid][3]));
}

extern "C" void kernel_launch(void* const* d_in, const int* in_sizes, int n_in,
                              void* d_out, int out_size) {
    const int*   U       = (const int*)d_in[0];
    const int*   V       = (const int*)d_in[1];
    const int*   adj_ent = (const int*)d_in[2];
    const int*   adj_rel = (const int*)d_in[3];
    const float* usr_emb = (const float*)d_in[4];
    const float* rel_emb = (const float*)d_in[5];
    const float* ent_emb = (const float*)d_in[6];
    const float* W       = (const float*)d_in[7];
    const float* bvec    = (const float*)d_in[8];
    float* out = (float*)d_out;

    const int B  = in_sizes[0];
    const int NR = in_sizes[5] / 64;

    kgcn_gather_kernel<<<B / 4, 256>>>(U, V, adj_ent, adj_rel, usr_emb,
                                       rel_emb, ent_emb, NR);
    kgcn_matvec_kernel<<<B / 4, 256>>>(U, usr_emb, W, bvec, out);
}

// round 10
// speedup vs baseline: 1.3474x; 1.3474x over previous
#include <cuda_runtime.h>

#define FULL 0xffffffffu

__device__ __forceinline__ float sigmoidf_(float y) {
    return __fdividef(1.f, 1.f + __expf(-y));
}

// ---- packed f32x2 helpers (sm_103a FFMA2 path) ----
__device__ __forceinline__ unsigned long long pack2_(float a, float b) {
    unsigned long long r;
    asm("mov.b64 %0, {%1, %2};" : "=l"(r) : "f"(a), "f"(b));
    return r;
}
__device__ __forceinline__ void fma2_(unsigned long long& d,
                                      unsigned long long a, unsigned long long b) {
    asm("fma.rn.f32x2 %0, %1, %2, %0;" : "+l"(d) : "l"(a), "l"(b));
}
__device__ __forceinline__ void add2_(unsigned long long& d,
                                      unsigned long long a, unsigned long long b) {
    asm("add.rn.f32x2 %0, %1, %2;" : "=l"(d) : "l"(a), "l"(b));
}
__device__ __forceinline__ float sum2_(unsigned long long v) {
    float lo, hi;
    asm("mov.b64 {%0, %1}, %2;" : "=f"(lo), "=f"(hi) : "l"(v));
    return lo + hi;
}

// KGCN fused (R8 architecture): one CTA per FOUR batch elements, 256 threads.
// Phase C: 4 interleaved softmax/gather chains, 68 LDG.128 in flight per warp.
// Matvec + Phase D: warp-autonomous; FMA work done with packed fma.rn.f32x2
// (one issue slot = 2 lane-FMAs) - halves the dominant FFMA issue cost.
__global__ void __launch_bounds__(256, 3) kgcn_kernel(
    const int* __restrict__ U, const int* __restrict__ V,
    const int* __restrict__ adj_ent, const int* __restrict__ adj_rel,
    const float* __restrict__ usr_emb, const float* __restrict__ rel_emb,
    const float* __restrict__ ent_emb, const float* __restrict__ Wg,
    const float* __restrict__ bg, float* __restrict__ out, int NR)
{
    __shared__ float user_sh[4][64];
    __shared__ float urel_sh[4][32];
    __shared__ int   nbr_sh[4][272];   // [0..255] hop2 ents, [256..271] hop1 ents
    __shared__ int   rel_sh[4][272];
    __shared__ float attn16_sh[4][16];
    __shared__ __align__(16) float x_sh[4][17][64];  // pre-matvec activations
    __shared__ __align__(16) float h_sh[4][17][64];  // post-sigmoid outputs
    __shared__ __align__(16) float x2_sh[4][64];
    __shared__ float red2_sh[4][4];

    const int tid   = threadIdx.x;
    const int col   = tid & 63;
    const int lane  = tid & 31;
    const int w     = tid >> 5;
    const int chunk = w & 3;          // 16-col chunk owned by this warp (matvec)
    const int par   = w >> 2;         // row parity (matvec)
    const int halfL = lane >> 4;      // d-half within warp (matvec)
    const int k15w  = lane & 15;
    const int mycol = chunk * 16 + k15w;

    const int b0 = 4 * blockIdx.x;
    int uu[4], vv[4];
    #pragma unroll
    for (int e = 0; e < 4; e++) { uu[e] = U[b0 + e]; vv[e] = V[b0 + e]; }

    // ---- Phase A: stage users, hop-1 adjacency; W half-column -> packed regs ----
    user_sh[tid >> 6][col] = usr_emb[uu[tid >> 6] * 64 + col];
    if (tid < 64) {
        int e = tid >> 4, j = tid & 15;
        nbr_sh[e][256 + j] = adj_ent[vv[e] * 16 + j];
        rel_sh[e][256 + j] = adj_rel[vv[e] * 16 + j];
    }
    unsigned long long Wp[16];   // Wp[i] packs W cols (2i, 2i+1) of my half
    #pragma unroll
    for (int i = 0; i < 16; i++) {
        float wa = Wg[(halfL * 32 + 2 * i) * 64 + mycol];
        float wb = Wg[(halfL * 32 + 2 * i + 1) * 64 + mycol];
        Wp[i] = pack2_(wa, wb);
    }
    const float bmy = bg[mycol];
    __syncthreads();

    // ---- Phase B: hop-2 adjacency (4 elems) + urel tables ----
    {
        int j = tid & 15, pr = tid >> 4;
        #pragma unroll
        for (int e = 0; e < 4; e++) {
            int p = nbr_sh[e][256 + pr];
            nbr_sh[e][tid] = adj_ent[p * 16 + j];
            rel_sh[e][tid] = adj_rel[p * 16 + j];
        }
    }
    {
        int r = tid >> 3;
        int c = (tid & 7) * 8;
        float pa[4] = {0.f, 0.f, 0.f, 0.f};
        if (r < NR) {
            const float4* rp = (const float4*)(rel_emb + r * 64 + c);
            float4 aa = rp[0], bb = rp[1];
            #pragma unroll
            for (int e = 0; e < 4; e++)
                pa[e] = aa.x * user_sh[e][c+0] + aa.y * user_sh[e][c+1]
                      + aa.z * user_sh[e][c+2] + aa.w * user_sh[e][c+3]
                      + bb.x * user_sh[e][c+4] + bb.y * user_sh[e][c+5]
                      + bb.z * user_sh[e][c+6] + bb.w * user_sh[e][c+7];
        }
        #pragma unroll
        for (int o = 4; o > 0; o >>= 1) {
            #pragma unroll
            for (int e = 0; e < 4; e++)
                pa[e] += __shfl_down_sync(FULL, pa[e], o);
        }
        if ((tid & 7) == 0 && r < NR) {
            #pragma unroll
            for (int e = 0; e < 4; e++) urel_sh[e][r] = pa[e];
        }
    }
    __syncthreads();

    // ---- Phase C: fused softmax + packed aggregation, 4 elems per warp ----
    {
        const int hlf16 = lane & 16;
        const int k15   = lane & 15;
        const int myrow = 2 * w + (lane >> 4);
        const ulonglong2* entu2 = (const ulonglong2*)ent_emb;  // 16B chunks

        float sc[4], mx[4], ev[4], sm[4], pp[4];
        #pragma unroll
        for (int e = 0; e < 4; e++)
            sc[e] = urel_sh[e][rel_sh[e][(myrow << 4) + k15]];
        #pragma unroll
        for (int e = 0; e < 4; e++) mx[e] = sc[e];
        #pragma unroll
        for (int o = 8; o > 0; o >>= 1) {
            #pragma unroll
            for (int e = 0; e < 4; e++)
                mx[e] = fmaxf(mx[e], __shfl_xor_sync(FULL, mx[e], o));
        }
        #pragma unroll
        for (int e = 0; e < 4; e++) { ev[e] = __expf(sc[e] - mx[e]); sm[e] = ev[e]; }
        #pragma unroll
        for (int o = 8; o > 0; o >>= 1) {
            #pragma unroll
            for (int e = 0; e < 4; e++)
                sm[e] += __shfl_xor_sync(FULL, sm[e], o);
        }
        #pragma unroll
        for (int e = 0; e < 4; e++) pp[e] = __fdividef(ev[e], sm[e]);

        const int* nb[4];
        #pragma unroll
        for (int e = 0; e < 4; e++) nb[e] = &nbr_sh[e][myrow << 4];
        unsigned long long accA[4], accB[4];
        #pragma unroll
        for (int e = 0; e < 4; e++) { accA[e] = 0ull; accB[e] = 0ull; }
        #pragma unroll
        for (int k = 0; k < 16; k++) {
            #pragma unroll
            for (int e = 0; e < 4; e++) {
                float pk = __shfl_sync(FULL, pp[e], hlf16 + k);
                unsigned long long pkk = pack2_(pk, pk);
                ulonglong2 t = entu2[(nb[e][k] << 4) + k15];
                fma2_(accA[e], pkk, t.x);
                fma2_(accB[e], pkk, t.y);
            }
        }
        #pragma unroll
        for (int e = 0; e < 4; e++) {
            ulonglong2 sv = entu2[(nbr_sh[e][256 + myrow] << 4) + k15];
            ulonglong2 o2;
            add2_(o2.x, accA[e], sv.x);
            add2_(o2.y, accB[e], sv.y);
            ((ulonglong2*)x_sh[e][myrow])[k15] = o2;
        }

        // hop-0 rows: warp e handles element e (e < 4)
        if (w < 4) {
            const int e = w;
            float s2 = urel_sh[e][rel_sh[e][256 + k15]];
            float mx2 = s2;
            mx2 = fmaxf(mx2, __shfl_xor_sync(FULL, mx2, 8));
            mx2 = fmaxf(mx2, __shfl_xor_sync(FULL, mx2, 4));
            mx2 = fmaxf(mx2, __shfl_xor_sync(FULL, mx2, 2));
            mx2 = fmaxf(mx2, __shfl_xor_sync(FULL, mx2, 1));
            float ev2 = __expf(s2 - mx2);
            float sm2 = ev2;
            sm2 += __shfl_xor_sync(FULL, sm2, 8);
            sm2 += __shfl_xor_sync(FULL, sm2, 4);
            sm2 += __shfl_xor_sync(FULL, sm2, 2);
            sm2 += __shfl_xor_sync(FULL, sm2, 1);
            float p2 = __fdividef(ev2, sm2);
            if (lane < 16) attn16_sh[e][lane] = p2;

            unsigned long long a2A = 0ull, a2B = 0ull;
            #pragma unroll
            for (int k = 0; k < 16; k++) {
                float pk = __shfl_sync(FULL, p2, hlf16 + k);
                unsigned long long pkk = pack2_(pk, pk);
                ulonglong2 t = entu2[(nbr_sh[e][256 + k] << 4) + k15];
                fma2_(a2A, pkk, t.x);
                fma2_(a2B, pkk, t.y);
            }
            ulonglong2 sv2 = entu2[(vv[e] << 4) + k15];
            if (lane < 16) {
                ulonglong2 o2;
                add2_(o2.x, a2A, sv2.x);
                add2_(o2.y, a2B, sv2.y);
                ((ulonglong2*)x_sh[e][16])[k15] = o2;
            }
        }
    }
    __syncthreads();

    // ---- Matvec: warp-autonomous, packed FMA, zero interior barriers.
    //      Warp w: cols chunk*16..+15, rows rr = par, par+2, ..; all 4 elems. ----
    {
        for (int rr = par; rr <= 16; rr += 2) {
            unsigned long long A0 = 0ull, A1 = 0ull, A2 = 0ull, A3 = 0ull;
            #pragma unroll
            for (int q = 0; q < 8; q++) {
                ulonglong2 v0 = *(const ulonglong2*)&x_sh[0][rr][halfL * 32 + 4*q];
                ulonglong2 v1 = *(const ulonglong2*)&x_sh[1][rr][halfL * 32 + 4*q];
                ulonglong2 v2 = *(const ulonglong2*)&x_sh[2][rr][halfL * 32 + 4*q];
                ulonglong2 v3 = *(const ulonglong2*)&x_sh[3][rr][halfL * 32 + 4*q];
                fma2_(A0, v0.x, Wp[2*q]); fma2_(A0, v0.y, Wp[2*q+1]);
                fma2_(A1, v1.x, Wp[2*q]); fma2_(A1, v1.y, Wp[2*q+1]);
                fma2_(A2, v2.x, Wp[2*q]); fma2_(A2, v2.y, Wp[2*q+1]);
                fma2_(A3, v3.x, Wp[2*q]); fma2_(A3, v3.y, Wp[2*q+1]);
            }
            float y0 = sum2_(A0), y1 = sum2_(A1), y2 = sum2_(A2), y3 = sum2_(A3);
            float t0 = y0 + __shfl_xor_sync(FULL, y0, 16);
            float t1 = y1 + __shfl_xor_sync(FULL, y1, 16);
            float t2 = y2 + __shfl_xor_sync(FULL, y2, 16);
            float t3 = y3 + __shfl_xor_sync(FULL, y3, 16);
            if (halfL == 0) {
                h_sh[0][rr][mycol] = sigmoidf_(t0 + bmy);
                h_sh[1][rr][mycol] = sigmoidf_(t1 + bmy);
                h_sh[2][rr][mycol] = sigmoidf_(t2 + bmy);
                h_sh[3][rr][mycol] = sigmoidf_(t3 + bmy);
            }
        }
    }
    __syncthreads();

    // ---- Phase D: iter-1 agg (thread per (e,col)) ----
    {
        const int e = tid >> 6;
        float a0 = 0.f, a1 = 0.f, a2 = 0.f, a3 = 0.f;
        #pragma unroll
        for (int k = 0; k < 16; k += 4) {
            a0 = fmaf(attn16_sh[e][k + 0], h_sh[e][k + 0][col], a0);
            a1 = fmaf(attn16_sh[e][k + 1], h_sh[e][k + 1][col], a1);
            a2 = fmaf(attn16_sh[e][k + 2], h_sh[e][k + 2][col], a2);
            a3 = fmaf(attn16_sh[e][k + 3], h_sh[e][k + 3][col], a3);
        }
        x2_sh[e][col] = h_sh[e][16][col] + ((a0 + a1) + (a2 + a3));
    }
    __syncthreads();

    // ---- Final matvec + tanh + dot(user) — warp-autonomous, packed ----
    {
        for (int e = par; e < 4; e += 2) {
            unsigned long long Acc = 0ull;
            #pragma unroll
            for (int q = 0; q < 8; q++) {
                ulonglong2 v = *(const ulonglong2*)&x2_sh[e][halfL * 32 + 4*q];
                fma2_(Acc, v.x, Wp[2*q]);
                fma2_(Acc, v.y, Wp[2*q+1]);
            }
            float y = sum2_(Acc);
            float tot = y + __shfl_xor_sync(FULL, y, 16);
            float item = tanhf(tot + bmy);
            float t = user_sh[e][mycol] * item;   // lanes L, L+16 duplicate
            t += __shfl_xor_sync(FULL, t, 8);
            t += __shfl_xor_sync(FULL, t, 4);
            t += __shfl_xor_sync(FULL, t, 2);
            t += __shfl_xor_sync(FULL, t, 1);
            if (lane == 0) red2_sh[e][chunk] = t;  // sum of this chunk's 16 cols
        }
    }
    __syncthreads();
    if (tid < 4)
        out[b0 + tid] = sigmoidf_((red2_sh[tid][0] + red2_sh[tid][1]) +
                                  (red2_sh[tid][2] + red2_sh[tid][3]));
}

extern "C" void kernel_launch(void* const* d_in, const int* in_sizes, int n_in,
                              void* d_out, int out_size) {
    const int*   U       = (const int*)d_in[0];
    const int*   V       = (const int*)d_in[1];
    const int*   adj_ent = (const int*)d_in[2];
    const int*   adj_rel = (const int*)d_in[3];
    const float* usr_emb = (const float*)d_in[4];
    const float* rel_emb = (const float*)d_in[5];
    const float* ent_emb = (const float*)d_in[6];
    const float* W       = (const float*)d_in[7];
    const float* bvec    = (const float*)d_in[8];
    float* out = (float*)d_out;

    const int B  = in_sizes[0];
    const int NR = in_sizes[5] / 64;

    kgcn_kernel<<<B / 4, 256>>>(U, V, adj_ent, adj_rel, usr_emb, rel_emb,
                                ent_emb, W, bvec, out, NR);
}

// round 11
// speedup vs baseline: 1.3753x; 1.0207x over previous
#include <cuda_runtime.h>

#define FULL 0xffffffffu

__device__ __forceinline__ float sigmoidf_(float y) {
    return __fdividef(1.f, 1.f + __expf(-y));
}

// ---- packed f32x2 helpers (sm_103a FFMA2 path) ----
__device__ __forceinline__ unsigned long long pack2_(float a, float b) {
    unsigned long long r;
    asm("mov.b64 %0, {%1, %2};" : "=l"(r) : "f"(a), "f"(b));
    return r;
}
__device__ __forceinline__ void fma2_(unsigned long long& d,
                                      unsigned long long a, unsigned long long b) {
    asm("fma.rn.f32x2 %0, %1, %2, %0;" : "+l"(d) : "l"(a), "l"(b));
}
__device__ __forceinline__ float sum2_(unsigned long long v) {
    float lo, hi;
    asm("mov.b64 {%0, %1}, %2;" : "=f"(lo), "=f"(hi) : "l"(v));
    return lo + hi;
}

// KGCN fused: one CTA per FOUR batch elements, 256 threads.
// Phase C: balanced half-warp task map - half-warp hw handles rows
// {hw>>2 (+4,+8,+12)} of elem hw&3 (4 interleaved chains), half-warps 0-3
// additionally take the 4 hop-0 rows (no duplicated halves). Self embedding
// initializes the accumulator so its load issues before the softmax chain.
// Matvec + Phase D: warp-autonomous packed fma.rn.f32x2 (R10, proven).
__global__ void __launch_bounds__(256, 3) kgcn_kernel(
    const int* __restrict__ U, const int* __restrict__ V,
    const int* __restrict__ adj_ent, const int* __restrict__ adj_rel,
    const float* __restrict__ usr_emb, const float* __restrict__ rel_emb,
    const float* __restrict__ ent_emb, const float* __restrict__ Wg,
    const float* __restrict__ bg, float* __restrict__ out, int NR)
{
    __shared__ float user_sh[4][64];
    __shared__ float urel_sh[4][32];
    __shared__ int   nbr_sh[4][272];   // [0..255] hop2 ents, [256..271] hop1 ents
    __shared__ int   rel_sh[4][272];
    __shared__ float attn16_sh[4][16];
    __shared__ int   v_sh[4];
    __shared__ __align__(16) float x_sh[4][17][64];  // pre-matvec activations
    __shared__ __align__(16) float h_sh[4][17][64];  // post-sigmoid outputs
    __shared__ __align__(16) float x2_sh[4][64];
    __shared__ float red2_sh[4][4];

    const int tid   = threadIdx.x;
    const int col   = tid & 63;
    const int lane  = tid & 31;
    const int w     = tid >> 5;
    const int chunk = w & 3;          // 16-col chunk owned by this warp (matvec)
    const int par   = w >> 2;         // row parity (matvec)
    const int halfL = lane >> 4;      // d-half within warp (matvec)
    const int k15w  = lane & 15;
    const int mycol = chunk * 16 + k15w;

    const int b0 = 4 * blockIdx.x;
    int uu[4], vv[4];
    #pragma unroll
    for (int e = 0; e < 4; e++) { uu[e] = U[b0 + e]; vv[e] = V[b0 + e]; }

    // ---- Phase A: stage users, v, hop-1 adjacency; W half-column -> packed regs ----
    user_sh[tid >> 6][col] = usr_emb[uu[tid >> 6] * 64 + col];
    if (tid < 4) v_sh[tid] = vv[tid];
    if (tid < 64) {
        int e = tid >> 4, j = tid & 15;
        nbr_sh[e][256 + j] = adj_ent[vv[e] * 16 + j];
        rel_sh[e][256 + j] = adj_rel[vv[e] * 16 + j];
    }
    unsigned long long Wp[16];   // Wp[i] packs W cols (2i, 2i+1) of my half
    #pragma unroll
    for (int i = 0; i < 16; i++) {
        float wa = Wg[(halfL * 32 + 2 * i) * 64 + mycol];
        float wb = Wg[(halfL * 32 + 2 * i + 1) * 64 + mycol];
        Wp[i] = pack2_(wa, wb);
    }
    const float bmy = bg[mycol];
    __syncthreads();

    // ---- Phase B: hop-2 adjacency (4 elems) + urel tables ----
    {
        int j = tid & 15, pr = tid >> 4;
        #pragma unroll
        for (int e = 0; e < 4; e++) {
            int p = nbr_sh[e][256 + pr];
            nbr_sh[e][tid] = adj_ent[p * 16 + j];
            rel_sh[e][tid] = adj_rel[p * 16 + j];
        }
    }
    {
        int r = tid >> 3;
        int c = (tid & 7) * 8;
        float pa[4] = {0.f, 0.f, 0.f, 0.f};
        if (r < NR) {
            const float4* rp = (const float4*)(rel_emb + r * 64 + c);
            float4 aa = rp[0], bb = rp[1];
            #pragma unroll
            for (int e = 0; e < 4; e++)
                pa[e] = aa.x * user_sh[e][c+0] + aa.y * user_sh[e][c+1]
                      + aa.z * user_sh[e][c+2] + aa.w * user_sh[e][c+3]
                      + bb.x * user_sh[e][c+4] + bb.y * user_sh[e][c+5]
                      + bb.z * user_sh[e][c+6] + bb.w * user_sh[e][c+7];
        }
        #pragma unroll
        for (int o = 4; o > 0; o >>= 1) {
            #pragma unroll
            for (int e = 0; e < 4; e++)
                pa[e] += __shfl_down_sync(FULL, pa[e], o);
        }
        if ((tid & 7) == 0 && r < NR) {
            #pragma unroll
            for (int e = 0; e < 4; e++) urel_sh[e][r] = pa[e];
        }
    }
    __syncthreads();

    // ---- Phase C: balanced half-warp tasks ----
    {
        const int hlf16 = lane & 16;
        const int k15   = lane & 15;
        const int hw    = 2 * w + halfL;      // half-warp id 0..15
        const int e     = hw & 3;             // element owned by this half-warp
        const int rbase = hw >> 2;            // base row (rows rbase, +4, +8, +12)
        const ulonglong2* entu2 = (const ulonglong2*)ent_emb;

        // self-initialized accumulators: loads issue before the softmax chains
        unsigned long long accA[4], accB[4];
        #pragma unroll
        for (int i = 0; i < 4; i++) {
            int r = rbase + 4 * i;
            ulonglong2 sv = entu2[(nbr_sh[e][256 + r] << 4) + k15];
            accA[i] = sv.x; accB[i] = sv.y;
        }

        // softmax for the 4 rows (independent chains, width-16 butterflies)
        float sc[4], mx[4], ev[4], sm[4], pp[4];
        #pragma unroll
        for (int i = 0; i < 4; i++)
            sc[i] = urel_sh[e][rel_sh[e][((rbase + 4 * i) << 4) + k15]];
        #pragma unroll
        for (int i = 0; i < 4; i++) mx[i] = sc[i];
        #pragma unroll
        for (int o = 8; o > 0; o >>= 1) {
            #pragma unroll
            for (int i = 0; i < 4; i++)
                mx[i] = fmaxf(mx[i], __shfl_xor_sync(FULL, mx[i], o));
        }
        #pragma unroll
        for (int i = 0; i < 4; i++) { ev[i] = __expf(sc[i] - mx[i]); sm[i] = ev[i]; }
        #pragma unroll
        for (int o = 8; o > 0; o >>= 1) {
            #pragma unroll
            for (int i = 0; i < 4; i++)
                sm[i] += __shfl_xor_sync(FULL, sm[i], o);
        }
        #pragma unroll
        for (int i = 0; i < 4; i++) pp[i] = __fdividef(ev[i], sm[i]);

        const int* nb[4];
        #pragma unroll
        for (int i = 0; i < 4; i++) nb[i] = &nbr_sh[e][(rbase + 4 * i) << 4];
        #pragma unroll
        for (int k = 0; k < 16; k++) {
            #pragma unroll
            for (int i = 0; i < 4; i++) {
                float pk = __shfl_sync(FULL, pp[i], hlf16 + k);
                unsigned long long pkk = pack2_(pk, pk);
                ulonglong2 t = entu2[(nb[i][k] << 4) + k15];
                fma2_(accA[i], pkk, t.x);
                fma2_(accB[i], pkk, t.y);
            }
        }
        #pragma unroll
        for (int i = 0; i < 4; i++) {
            ulonglong2 o2; o2.x = accA[i]; o2.y = accB[i];
            ((ulonglong2*)x_sh[e][rbase + 4 * i])[k15] = o2;
        }

        // hop-0 rows: half-warps 0..3 (warps 0-1, both halves active) each
        // take ONE hop-0 row - no duplicated halves.
        if (hw < 4) {
            const int e2 = hw;
            unsigned long long a2A, a2B;
            {
                ulonglong2 sv2 = entu2[(v_sh[e2] << 4) + k15];
                a2A = sv2.x; a2B = sv2.y;
            }
            float s2 = urel_sh[e2][rel_sh[e2][256 + k15]];
            float mx2 = s2;
            mx2 = fmaxf(mx2, __shfl_xor_sync(FULL, mx2, 8));
            mx2 = fmaxf(mx2, __shfl_xor_sync(FULL, mx2, 4));
            mx2 = fmaxf(mx2, __shfl_xor_sync(FULL, mx2, 2));
            mx2 = fmaxf(mx2, __shfl_xor_sync(FULL, mx2, 1));
            float ev2 = __expf(s2 - mx2);
            float sm2 = ev2;
            sm2 += __shfl_xor_sync(FULL, sm2, 8);
            sm2 += __shfl_xor_sync(FULL, sm2, 4);
            sm2 += __shfl_xor_sync(FULL, sm2, 2);
            sm2 += __shfl_xor_sync(FULL, sm2, 1);
            float p2 = __fdividef(ev2, sm2);
            attn16_sh[e2][k15] = p2;

            #pragma unroll
            for (int k = 0; k < 16; k++) {
                float pk = __shfl_sync(FULL, p2, hlf16 + k);
                unsigned long long pkk = pack2_(pk, pk);
                ulonglong2 t = entu2[(nbr_sh[e2][256 + k] << 4) + k15];
                fma2_(a2A, pkk, t.x);
                fma2_(a2B, pkk, t.y);
            }
            ulonglong2 o2; o2.x = a2A; o2.y = a2B;
            ((ulonglong2*)x_sh[e2][16])[k15] = o2;
        }
    }
    __syncthreads();

    // ---- Matvec: warp-autonomous, packed FMA, zero interior barriers. ----
    {
        for (int rr = par; rr <= 16; rr += 2) {
            unsigned long long A0 = 0ull, A1 = 0ull, A2 = 0ull, A3 = 0ull;
            #pragma unroll
            for (int q = 0; q < 8; q++) {
                ulonglong2 v0 = *(const ulonglong2*)&x_sh[0][rr][halfL * 32 + 4*q];
                ulonglong2 v1 = *(const ulonglong2*)&x_sh[1][rr][halfL * 32 + 4*q];
                ulonglong2 v2 = *(const ulonglong2*)&x_sh[2][rr][halfL * 32 + 4*q];
                ulonglong2 v3 = *(const ulonglong2*)&x_sh[3][rr][halfL * 32 + 4*q];
                fma2_(A0, v0.x, Wp[2*q]); fma2_(A0, v0.y, Wp[2*q+1]);
                fma2_(A1, v1.x, Wp[2*q]); fma2_(A1, v1.y, Wp[2*q+1]);
                fma2_(A2, v2.x, Wp[2*q]); fma2_(A2, v2.y, Wp[2*q+1]);
                fma2_(A3, v3.x, Wp[2*q]); fma2_(A3, v3.y, Wp[2*q+1]);
            }
            float y0 = sum2_(A0), y1 = sum2_(A1), y2 = sum2_(A2), y3 = sum2_(A3);
            float t0 = y0 + __shfl_xor_sync(FULL, y0, 16);
            float t1 = y1 + __shfl_xor_sync(FULL, y1, 16);
            float t2 = y2 + __shfl_xor_sync(FULL, y2, 16);
            float t3 = y3 + __shfl_xor_sync(FULL, y3, 16);
            if (halfL == 0) {
                h_sh[0][rr][mycol] = sigmoidf_(t0 + bmy);
                h_sh[1][rr][mycol] = sigmoidf_(t1 + bmy);
                h_sh[2][rr][mycol] = sigmoidf_(t2 + bmy);
                h_sh[3][rr][mycol] = sigmoidf_(t3 + bmy);
            }
        }
    }
    __syncthreads();

    // ---- Phase D: iter-1 agg (thread per (e,col)) ----
    {
        const int e = tid >> 6;
        float a0 = 0.f, a1 = 0.f, a2 = 0.f, a3 = 0.f;
        #pragma unroll
        for (int k = 0; k < 16; k += 4) {
            a0 = fmaf(attn16_sh[e][k + 0], h_sh[e][k + 0][col], a0);
            a1 = fmaf(attn16_sh[e][k + 1], h_sh[e][k + 1][col], a1);
            a2 = fmaf(attn16_sh[e][k + 2], h_sh[e][k + 2][col], a2);
            a3 = fmaf(attn16_sh[e][k + 3], h_sh[e][k + 3][col], a3);
        }
        x2_sh[e][col] = h_sh[e][16][col] + ((a0 + a1) + (a2 + a3));
    }
    __syncthreads();

    // ---- Final matvec + tanh + dot(user) — warp-autonomous, packed ----
    {
        for (int e = par; e < 4; e += 2) {
            unsigned long long Acc = 0ull;
            #pragma unroll
            for (int q = 0; q < 8; q++) {
                ulonglong2 v = *(const ulonglong2*)&x2_sh[e][halfL * 32 + 4*q];
                fma2_(Acc, v.x, Wp[2*q]);
                fma2_(Acc, v.y, Wp[2*q+1]);
            }
            float y = sum2_(Acc);
            float tot = y + __shfl_xor_sync(FULL, y, 16);
            float item = tanhf(tot + bmy);
            float t = user_sh[e][mycol] * item;   // lanes L, L+16 duplicate
            t += __shfl_xor_sync(FULL, t, 8);
            t += __shfl_xor_sync(FULL, t, 4);
            t += __shfl_xor_sync(FULL, t, 2);
            t += __shfl_xor_sync(FULL, t, 1);
            if (lane == 0) red2_sh[e][chunk] = t;  // sum of this chunk's 16 cols
        }
    }
    __syncthreads();
    if (tid < 4)
        out[b0 + tid] = sigmoidf_((red2_sh[tid][0] + red2_sh[tid][1]) +
                                  (red2_sh[tid][2] + red2_sh[tid][3]));
}

extern "C" void kernel_launch(void* const* d_in, const int* in_sizes, int n_in,
                              void* d_out, int out_size) {
    const int*   U       = (const int*)d_in[0];
    const int*   V       = (const int*)d_in[1];
    const int*   adj_ent = (const int*)d_in[2];
    const int*   adj_rel = (const int*)d_in[3];
    const float* usr_emb = (const float*)d_in[4];
    const float* rel_emb = (const float*)d_in[5];
    const float* ent_emb = (const float*)d_in[6];
    const float* W       = (const float*)d_in[7];
    const float* bvec    = (const float*)d_in[8];
    float* out = (float*)d_out;

    const int B  = in_sizes[0];
    const int NR = in_sizes[5] / 64;

    kgcn_kernel<<<B / 4, 256>>>(U, V, adj_ent, adj_rel, usr_emb, rel_emb,
                                ent_emb, W, bvec, out, NR);
}

// round 12
// speedup vs baseline: 1.3758x; 1.0003x over previous
#include <cuda_runtime.h>

#define FULL 0xffffffffu

__device__ __forceinline__ float sigmoidf_(float y) {
    return __fdividef(1.f, 1.f + __expf(-y));
}

// ---- packed f32x2 helpers (sm_103a FFMA2 path) ----
__device__ __forceinline__ unsigned long long pack2_(float a, float b) {
    unsigned long long r;
    asm("mov.b64 %0, {%1, %2};" : "=l"(r) : "f"(a), "f"(b));
    return r;
}
__device__ __forceinline__ void fma2_(unsigned long long& d,
                                      unsigned long long a, unsigned long long b) {
    asm("fma.rn.f32x2 %0, %1, %2, %0;" : "+l"(d) : "l"(a), "l"(b));
}
__device__ __forceinline__ float sum2_(unsigned long long v) {
    float lo, hi;
    asm("mov.b64 {%0, %1}, %2;" : "=f"(lo), "=f"(hi) : "l"(v));
    return lo + hi;
}

// KGCN fused: one CTA per FOUR batch elements, 256 threads, 4 CTAs/SM.
// Phase C: balanced half-warp task map (R11). W packed registers loaded AFTER
// Phase C so the register lifetimes don't stack -> fits 64 regs -> occ 4.
// Matvec + Phase D: warp-autonomous packed fma.rn.f32x2.
__global__ void __launch_bounds__(256, 4) kgcn_kernel(
    const int* __restrict__ U, const int* __restrict__ V,
    const int* __restrict__ adj_ent, const int* __restrict__ adj_rel,
    const float* __restrict__ usr_emb, const float* __restrict__ rel_emb,
    const float* __restrict__ ent_emb, const float* __restrict__ Wg,
    const float* __restrict__ bg, float* __restrict__ out, int NR)
{
    __shared__ float user_sh[4][64];
    __shared__ float urel_sh[4][32];
    __shared__ int   nbr_sh[4][272];   // [0..255] hop2 ents, [256..271] hop1 ents
    __shared__ int   rel_sh[4][272];
    __shared__ float attn16_sh[4][16];
    __shared__ int   v_sh[4];
    __shared__ __align__(16) float x_sh[4][17][64];  // pre-matvec activations
    __shared__ __align__(16) float h_sh[4][17][64];  // post-sigmoid outputs
    __shared__ __align__(16) float x2_sh[4][64];
    __shared__ float red2_sh[4][4];

    const int tid   = threadIdx.x;
    const int col   = tid & 63;
    const int lane  = tid & 31;
    const int w     = tid >> 5;
    const int chunk = w & 3;          // 16-col chunk owned by this warp (matvec)
    const int par   = w >> 2;         // row parity (matvec)
    const int halfL = lane >> 4;      // d-half within warp (matvec)
    const int k15w  = lane & 15;
    const int mycol = chunk * 16 + k15w;

    const int b0 = 4 * blockIdx.x;
    int uu[4], vv[4];
    #pragma unroll
    for (int e = 0; e < 4; e++) { uu[e] = U[b0 + e]; vv[e] = V[b0 + e]; }

    // ---- Phase A: stage users, v, hop-1 adjacency ----
    user_sh[tid >> 6][col] = usr_emb[uu[tid >> 6] * 64 + col];
    if (tid < 4) v_sh[tid] = vv[tid];
    if (tid < 64) {
        int e = tid >> 4, j = tid & 15;
        nbr_sh[e][256 + j] = adj_ent[vv[e] * 16 + j];
        rel_sh[e][256 + j] = adj_rel[vv[e] * 16 + j];
    }
    __syncthreads();

    // ---- Phase B: hop-2 adjacency (4 elems) + urel tables ----
    {
        int j = tid & 15, pr = tid >> 4;
        #pragma unroll
        for (int e = 0; e < 4; e++) {
            int p = nbr_sh[e][256 + pr];
            nbr_sh[e][tid] = adj_ent[p * 16 + j];
            rel_sh[e][tid] = adj_rel[p * 16 + j];
        }
    }
    {
        int r = tid >> 3;
        int c = (tid & 7) * 8;
        float pa[4] = {0.f, 0.f, 0.f, 0.f};
        if (r < NR) {
            const float4* rp = (const float4*)(rel_emb + r * 64 + c);
            float4 aa = rp[0], bb = rp[1];
            #pragma unroll
            for (int e = 0; e < 4; e++)
                pa[e] = aa.x * user_sh[e][c+0] + aa.y * user_sh[e][c+1]
                      + aa.z * user_sh[e][c+2] + aa.w * user_sh[e][c+3]
                      + bb.x * user_sh[e][c+4] + bb.y * user_sh[e][c+5]
                      + bb.z * user_sh[e][c+6] + bb.w * user_sh[e][c+7];
        }
        #pragma unroll
        for (int o = 4; o > 0; o >>= 1) {
            #pragma unroll
            for (int e = 0; e < 4; e++)
                pa[e] += __shfl_down_sync(FULL, pa[e], o);
        }
        if ((tid & 7) == 0 && r < NR) {
            #pragma unroll
            for (int e = 0; e < 4; e++) urel_sh[e][r] = pa[e];
        }
    }
    __syncthreads();

    // ---- Phase C: balanced half-warp tasks ----
    {
        const int hlf16 = lane & 16;
        const int k15   = lane & 15;
        const int hw    = 2 * w + halfL;      // half-warp id 0..15
        const int e     = hw & 3;             // element owned by this half-warp
        const int rbase = hw >> 2;            // base row (rows rbase, +4, +8, +12)
        const ulonglong2* entu2 = (const ulonglong2*)ent_emb;

        // self-initialized accumulators: loads issue before the softmax chains
        unsigned long long accA[4], accB[4];
        #pragma unroll
        for (int i = 0; i < 4; i++) {
            int r = rbase + 4 * i;
            ulonglong2 sv = entu2[(nbr_sh[e][256 + r] << 4) + k15];
            accA[i] = sv.x; accB[i] = sv.y;
        }

        // softmax for the 4 rows (independent chains, width-16 butterflies)
        float sc[4], mx[4], ev[4], sm[4], pp[4];
        #pragma unroll
        for (int i = 0; i < 4; i++)
            sc[i] = urel_sh[e][rel_sh[e][((rbase + 4 * i) << 4) + k15]];
        #pragma unroll
        for (int i = 0; i < 4; i++) mx[i] = sc[i];
        #pragma unroll
        for (int o = 8; o > 0; o >>= 1) {
            #pragma unroll
            for (int i = 0; i < 4; i++)
                mx[i] = fmaxf(mx[i], __shfl_xor_sync(FULL, mx[i], o));
        }
        #pragma unroll
        for (int i = 0; i < 4; i++) { ev[i] = __expf(sc[i] - mx[i]); sm[i] = ev[i]; }
        #pragma unroll
        for (int o = 8; o > 0; o >>= 1) {
            #pragma unroll
            for (int i = 0; i < 4; i++)
                sm[i] += __shfl_xor_sync(FULL, sm[i], o);
        }
        #pragma unroll
        for (int i = 0; i < 4; i++) pp[i] = __fdividef(ev[i], sm[i]);

        const int* nb[4];
        #pragma unroll
        for (int i = 0; i < 4; i++) nb[i] = &nbr_sh[e][(rbase + 4 * i) << 4];
        #pragma unroll
        for (int k = 0; k < 16; k++) {
            #pragma unroll
            for (int i = 0; i < 4; i++) {
                float pk = __shfl_sync(FULL, pp[i], hlf16 + k);
                unsigned long long pkk = pack2_(pk, pk);
                ulonglong2 t = entu2[(nb[i][k] << 4) + k15];
                fma2_(accA[i], pkk, t.x);
                fma2_(accB[i], pkk, t.y);
            }
        }
        #pragma unroll
        for (int i = 0; i < 4; i++) {
            ulonglong2 o2; o2.x = accA[i]; o2.y = accB[i];
            ((ulonglong2*)x_sh[e][rbase + 4 * i])[k15] = o2;
        }

        // hop-0 rows: half-warps 0..3 each take ONE hop-0 row (no dup halves)
        if (hw < 4) {
            const int e2 = hw;
            unsigned long long a2A, a2B;
            {
                ulonglong2 sv2 = entu2[(v_sh[e2] << 4) + k15];
                a2A = sv2.x; a2B = sv2.y;
            }
            float s2 = urel_sh[e2][rel_sh[e2][256 + k15]];
            float mx2 = s2;
            mx2 = fmaxf(mx2, __shfl_xor_sync(FULL, mx2, 8));
            mx2 = fmaxf(mx2, __shfl_xor_sync(FULL, mx2, 4));
            mx2 = fmaxf(mx2, __shfl_xor_sync(FULL, mx2, 2));
            mx2 = fmaxf(mx2, __shfl_xor_sync(FULL, mx2, 1));
            float ev2 = __expf(s2 - mx2);
            float sm2 = ev2;
            sm2 += __shfl_xor_sync(FULL, sm2, 8);
            sm2 += __shfl_xor_sync(FULL, sm2, 4);
            sm2 += __shfl_xor_sync(FULL, sm2, 2);
            sm2 += __shfl_xor_sync(FULL, sm2, 1);
            float p2 = __fdividef(ev2, sm2);
            attn16_sh[e2][k15] = p2;

            #pragma unroll
            for (int k = 0; k < 16; k++) {
                float pk = __shfl_sync(FULL, p2, hlf16 + k);
                unsigned long long pkk = pack2_(pk, pk);
                ulonglong2 t = entu2[(nbr_sh[e2][256 + k] << 4) + k15];
                fma2_(a2A, pkk, t.x);
                fma2_(a2B, pkk, t.y);
            }
            ulonglong2 o2; o2.x = a2A; o2.y = a2B;
            ((ulonglong2*)x_sh[e2][16])[k15] = o2;
        }
    }

    // ---- W half-column -> packed regs (AFTER Phase C: lifetimes don't stack) ----
    unsigned long long Wp[16];   // Wp[i] packs W cols (2i, 2i+1) of my half
    #pragma unroll
    for (int i = 0; i < 16; i++) {
        float wa = Wg[(halfL * 32 + 2 * i) * 64 + mycol];
        float wb = Wg[(halfL * 32 + 2 * i + 1) * 64 + mycol];
        Wp[i] = pack2_(wa, wb);
    }
    const float bmy = bg[mycol];
    __syncthreads();

    // ---- Matvec: warp-autonomous, packed FMA, zero interior barriers. ----
    {
        for (int rr = par; rr <= 16; rr += 2) {
            unsigned long long A0 = 0ull, A1 = 0ull, A2 = 0ull, A3 = 0ull;
            #pragma unroll
            for (int q = 0; q < 8; q++) {
                ulonglong2 v0 = *(const ulonglong2*)&x_sh[0][rr][halfL * 32 + 4*q];
                ulonglong2 v1 = *(const ulonglong2*)&x_sh[1][rr][halfL * 32 + 4*q];
                ulonglong2 v2 = *(const ulonglong2*)&x_sh[2][rr][halfL * 32 + 4*q];
                ulonglong2 v3 = *(const ulonglong2*)&x_sh[3][rr][halfL * 32 + 4*q];
                fma2_(A0, v0.x, Wp[2*q]); fma2_(A0, v0.y, Wp[2*q+1]);
                fma2_(A1, v1.x, Wp[2*q]); fma2_(A1, v1.y, Wp[2*q+1]);
                fma2_(A2, v2.x, Wp[2*q]); fma2_(A2, v2.y, Wp[2*q+1]);
                fma2_(A3, v3.x, Wp[2*q]); fma2_(A3, v3.y, Wp[2*q+1]);
            }
            float y0 = sum2_(A0), y1 = sum2_(A1), y2 = sum2_(A2), y3 = sum2_(A3);
            float t0 = y0 + __shfl_xor_sync(FULL, y0, 16);
            float t1 = y1 + __shfl_xor_sync(FULL, y1, 16);
            float t2 = y2 + __shfl_xor_sync(FULL, y2, 16);
            float t3 = y3 + __shfl_xor_sync(FULL, y3, 16);
            if (halfL == 0) {
                h_sh[0][rr][mycol] = sigmoidf_(t0 + bmy);
                h_sh[1][rr][mycol] = sigmoidf_(t1 + bmy);
                h_sh[2][rr][mycol] = sigmoidf_(t2 + bmy);
                h_sh[3][rr][mycol] = sigmoidf_(t3 + bmy);
            }
        }
    }
    __syncthreads();

    // ---- Phase D: iter-1 agg (thread per (e,col)) ----
    {
        const int e = tid >> 6;
        float a0 = 0.f, a1 = 0.f, a2 = 0.f, a3 = 0.f;
        #pragma unroll
        for (int k = 0; k < 16; k += 4) {
            a0 = fmaf(attn16_sh[e][k + 0], h_sh[e][k + 0][col], a0);
            a1 = fmaf(attn16_sh[e][k + 1], h_sh[e][k + 1][col], a1);
            a2 = fmaf(attn16_sh[e][k + 2], h_sh[e][k + 2][col], a2);
            a3 = fmaf(attn16_sh[e][k + 3], h_sh[e][k + 3][col], a3);
        }
        x2_sh[e][col] = h_sh[e][16][col] + ((a0 + a1) + (a2 + a3));
    }
    __syncthreads();

    // ---- Final matvec + tanh + dot(user) — warp-autonomous, packed ----
    {
        for (int e = par; e < 4; e += 2) {
            unsigned long long Acc = 0ull;
            #pragma unroll
            for (int q = 0; q < 8; q++) {
                ulonglong2 v = *(const ulonglong2*)&x2_sh[e][halfL * 32 + 4*q];
                fma2_(Acc, v.x, Wp[2*q]);
                fma2_(Acc, v.y, Wp[2*q+1]);
            }
            float y = sum2_(Acc);
            float tot = y + __shfl_xor_sync(FULL, y, 16);
            float item = tanhf(tot + bmy);
            float t = user_sh[e][mycol] * item;   // lanes L, L+16 duplicate
            t += __shfl_xor_sync(FULL, t, 8);
            t += __shfl_xor_sync(FULL, t, 4);
            t += __shfl_xor_sync(FULL, t, 2);
            t += __shfl_xor_sync(FULL, t, 1);
            if (lane == 0) red2_sh[e][chunk] = t;  // sum of this chunk's 16 cols
        }
    }
    __syncthreads();
    if (tid < 4)
        out[b0 + tid] = sigmoidf_((red2_sh[tid][0] + red2_sh[tid][1]) +
                                  (red2_sh[tid][2] + red2_sh[tid][3]));
}

extern "C" void kernel_launch(void* const* d_in, const int* in_sizes, int n_in,
                              void* d_out, int out_size) {
    const int*   U       = (const int*)d_in[0];
    const int*   V       = (const int*)d_in[1];
    const int*   adj_ent = (const int*)d_in[2];
    const int*   adj_rel = (const int*)d_in[3];
    const float* usr_emb = (const float*)d_in[4];
    const float* rel_emb = (const float*)d_in[5];
    const float* ent_emb = (const float*)d_in[6];
    const float* W       = (const float*)d_in[7];
    const float* bvec    = (const float*)d_in[8];
    float* out = (float*)d_out;

    const int B  = in_sizes[0];
    const int NR = in_sizes[5] / 64;

    kgcn_kernel<<<B / 4, 256>>>(U, V, adj_ent, adj_rel, usr_emb, rel_emb,
                                ent_emb, W, bvec, out, NR);
}